// round 15
// baseline (speedup 1.0000x reference)
#include <cuda_runtime.h>
#include <cuda_fp16.h>
#include <cstdint>

#define N_NODES 100000
#define N_EDGES_MAX 3200000
#define IN_C 64
#define HID_C 64
#define OUT_C 32
#define SCAN_BLOCKS 98   // 98 * 1024 >= N_NODES

// Scratch (static __device__ arrays per harness rules)
__device__ __align__(16) float  g_pre [(size_t)N_NODES * HID_C];  // x@W1r + b1l
__device__ __align__(16) __half g_xh  [(size_t)N_NODES * IN_C];   // x in fp16
__device__ __align__(16) __half g_p2h [(size_t)N_NODES * OUT_C];  // h@W2l fp16
__device__ __align__(16) int    g_csr [N_EDGES_MAX];
__device__ __align__(16) int    g_rank[N_EDGES_MAX];
__device__ __align__(16) int    g_degi[N_NODES];
__device__ __align__(16) int    g_rowstart[N_NODES + 1];
__device__ __align__(16) int    g_bsum[SCAN_BLOCKS];
__device__ int g_scan_count;

static __device__ __forceinline__ unsigned h2_bits(__half2 h) {
    return *reinterpret_cast<const unsigned*>(&h);
}
static __device__ __forceinline__ __half2 u2h(unsigned u) {
    return *reinterpret_cast<const __half2*>(&u);
}
static __device__ __forceinline__ float2 u32_to_f2(unsigned u) {
    return __half22float2(*reinterpret_cast<const __half2*>(&u));
}
// --- packed f32x2 helpers (FFMA2; PTX-only) ---
static __device__ __forceinline__ unsigned long long dup2(float v) {
    unsigned long long r;
    asm("mov.b64 %0, {%1, %1};" : "=l"(r) : "f"(v));
    return r;
}
static __device__ __forceinline__ unsigned long long fma2(
    unsigned long long a, unsigned long long b, unsigned long long c) {
    unsigned long long d;
    asm("fma.rn.f32x2 %0, %1, %2, %3;" : "=l"(d) : "l"(a), "l"(b), "l"(c));
    return d;
}
static __device__ __forceinline__ void unpack2(unsigned long long v,
                                               float& lo, float& hi) {
    asm("mov.b64 {%0, %1}, %2;" : "=f"(lo), "=f"(hi) : "l"(v));
}

// ---------------------------------------------------------------------------
// Kernel 1: degree histogram + per-edge rank + x -> fp16. int4 edge loads.
// ---------------------------------------------------------------------------
__global__ void hist_xconv_kernel(const int* __restrict__ ei,
                                  const float* __restrict__ x, int E) {
    int t = blockIdx.x * blockDim.x + threadIdx.x;
    int e0 = t * 4;
    int d[4];
    bool full = (e0 + 4 <= E);
    if (full) {
        int4 dv = *(const int4*)(ei + (size_t)E + e0);
        d[0] = dv.x; d[1] = dv.y; d[2] = dv.z; d[3] = dv.w;
    } else {
#pragma unroll
        for (int j = 0; j < 4; j++) {
            int e = e0 + j;
            if (e < E) d[j] = ei[(size_t)E + e];
        }
    }
    int r[4];
#pragma unroll
    for (int j = 0; j < 4; j++) {
        int e = e0 + j;
        if (e < E) r[j] = atomicAdd(&g_degi[d[j]], 1);
    }
    if (full) {
        *(int4*)(g_rank + e0) = make_int4(r[0], r[1], r[2], r[3]);
    } else {
#pragma unroll
        for (int j = 0; j < 4; j++) {
            int e = e0 + j;
            if (e < E) g_rank[e] = r[j];
        }
    }
    size_t xi = (size_t)t * 8;
    if (xi + 8 <= (size_t)N_NODES * IN_C) {
        float4 f0 = ((const float4*)x)[t * 2];
        float4 f1 = ((const float4*)x)[t * 2 + 1];
        __half2 h0 = __floats2half2_rn(f0.x, f0.y);
        __half2 h1 = __floats2half2_rn(f0.z, f0.w);
        __half2 h2 = __floats2half2_rn(f1.x, f1.y);
        __half2 h3 = __floats2half2_rn(f1.z, f1.w);
        uint4 packed = make_uint4(h2_bits(h0), h2_bits(h1), h2_bits(h2), h2_bits(h3));
        ((uint4*)g_xh)[t] = packed;
    }
}

// ---------------------------------------------------------------------------
// Kernel 2: fused scan (single kernel, global barrier via atomic counter).
// ---------------------------------------------------------------------------
__global__ __launch_bounds__(1024) void scan_fused_kernel() {
    __shared__ int ssum[1024];
    __shared__ int sbs[128];
    __shared__ int sorig[128];
    __shared__ int s_boff;
    int t = threadIdx.x;
    int b = blockIdx.x;
    int node = b * 1024 + t;
    int v = (node < N_NODES) ? g_degi[node] : 0;
    ssum[t] = v;
    __syncthreads();
    for (int off = 1; off < 1024; off <<= 1) {
        int u = (t >= off) ? ssum[t - off] : 0;
        __syncthreads();
        ssum[t] += u;
        __syncthreads();
    }
    int lexcl = ssum[t] - v;
    if (t == 1023) {
        g_bsum[b] = ssum[t];
        __threadfence();
        atomicAdd(&g_scan_count, 1);
    }
    if (t == 0) {
        while (atomicAdd(&g_scan_count, 0) < SCAN_BLOCKS) { }
    }
    __syncthreads();
    __threadfence();
    int bv = (t < SCAN_BLOCKS) ? g_bsum[t] : 0;
    if (t < 128) { sbs[t] = bv; sorig[t] = bv; }
    __syncthreads();
    for (int off = 1; off < 128; off <<= 1) {
        int u = (t >= off && t < 128) ? sbs[t - off] : 0;
        __syncthreads();
        if (t < 128) sbs[t] += u;
        __syncthreads();
    }
    if (t == 0) s_boff = sbs[b] - sorig[b];
    __syncthreads();
    if (node < N_NODES) g_rowstart[node] = lexcl + s_boff;
    if (b == 0 && t == 0) g_rowstart[N_NODES] = sbs[SCAN_BLOCKS - 1];
}

// ---------------------------------------------------------------------------
// Kernel 3: fill CSR — no atomics; int4 loads for src/dst/rank.
// ---------------------------------------------------------------------------
__global__ void fill_kernel(const int* __restrict__ ei, int E) {
    int e0 = (blockIdx.x * blockDim.x + threadIdx.x) * 4;
    int s[4], d[4], r[4];
    bool full = (e0 + 4 <= E);
    if (full) {
        int4 sv = *(const int4*)(ei + e0);
        int4 dv = *(const int4*)(ei + (size_t)E + e0);
        int4 rv = *(const int4*)(g_rank + e0);
        s[0] = sv.x; s[1] = sv.y; s[2] = sv.z; s[3] = sv.w;
        d[0] = dv.x; d[1] = dv.y; d[2] = dv.z; d[3] = dv.w;
        r[0] = rv.x; r[1] = rv.y; r[2] = rv.z; r[3] = rv.w;
    } else {
#pragma unroll
        for (int j = 0; j < 4; j++) {
            int e = e0 + j;
            if (e < E) {
                s[j] = ei[e];
                d[j] = ei[(size_t)E + e];
                r[j] = g_rank[e];
            }
        }
    }
    int base[4];
#pragma unroll
    for (int j = 0; j < 4; j++) {
        int e = e0 + j;
        if (e < E) base[j] = g_rowstart[d[j]];
    }
#pragma unroll
    for (int j = 0; j < 4; j++) {
        int e = e0 + j;
        if (e < E) g_csr[base[j] + r[j]] = s[j];
    }
}

// ---------------------------------------------------------------------------
// FFMA2 GEMM core over a local smem A tile.
// ---------------------------------------------------------------------------
#define GEMM_CORE_L(A4, sB, accP, lbase, cg)                                  \
    {                                                                         \
        const ulonglong2* sBp = (const ulonglong2*)(sB);                      \
        _Pragma("unroll 4")                                                   \
        for (int k4 = 0; k4 < 16; k4++) {                                     \
            ulonglong2 b0 = sBp[(k4 * 4 + 0) * 16 + (cg)];                    \
            ulonglong2 b1 = sBp[(k4 * 4 + 1) * 16 + (cg)];                    \
            ulonglong2 b2 = sBp[(k4 * 4 + 2) * 16 + (cg)];                    \
            ulonglong2 b3 = sBp[(k4 * 4 + 3) * 16 + (cg)];                    \
            _Pragma("unroll")                                                 \
            for (int m = 0; m < 8; m++) {                                     \
                int lrow = (lbase) + m;                                       \
                float4 a = (A4)[lrow * 16 + k4];                              \
                unsigned long long ax = dup2(a.x), ay = dup2(a.y);            \
                unsigned long long az = dup2(a.z), aw = dup2(a.w);            \
                accP[m][0] = fma2(ax, b0.x, accP[m][0]);                      \
                accP[m][1] = fma2(ax, b0.y, accP[m][1]);                      \
                accP[m][0] = fma2(ay, b1.x, accP[m][0]);                      \
                accP[m][1] = fma2(ay, b1.y, accP[m][1]);                      \
                accP[m][0] = fma2(az, b2.x, accP[m][0]);                      \
                accP[m][1] = fma2(az, b2.y, accP[m][1]);                      \
                accP[m][0] = fma2(aw, b3.x, accP[m][0]);                      \
                accP[m][1] = fma2(aw, b3.y, accP[m][1]);                      \
            }                                                                 \
        }                                                                     \
    }

// Global-A variant (for gemmR only).
#define GEMM_CORE(A4, sB, accP, nodeBase, cg)                                 \
    {                                                                         \
        const ulonglong2* sBp = (const ulonglong2*)(sB);                      \
        _Pragma("unroll 4")                                                   \
        for (int k4 = 0; k4 < 16; k4++) {                                     \
            ulonglong2 b0 = sBp[(k4 * 4 + 0) * 16 + (cg)];                    \
            ulonglong2 b1 = sBp[(k4 * 4 + 1) * 16 + (cg)];                    \
            ulonglong2 b2 = sBp[(k4 * 4 + 2) * 16 + (cg)];                    \
            ulonglong2 b3 = sBp[(k4 * 4 + 3) * 16 + (cg)];                    \
            _Pragma("unroll")                                                 \
            for (int m = 0; m < 8; m++) {                                     \
                int node = min((nodeBase) + m, N_NODES - 1);                  \
                float4 a = (A4)[(size_t)node * 16 + k4];                      \
                unsigned long long ax = dup2(a.x), ay = dup2(a.y);            \
                unsigned long long az = dup2(a.z), aw = dup2(a.w);            \
                accP[m][0] = fma2(ax, b0.x, accP[m][0]);                      \
                accP[m][1] = fma2(ax, b0.y, accP[m][1]);                      \
                accP[m][0] = fma2(ay, b1.x, accP[m][0]);                      \
                accP[m][1] = fma2(ay, b1.y, accP[m][1]);                      \
                accP[m][0] = fma2(az, b2.x, accP[m][0]);                      \
                accP[m][1] = fma2(az, b2.y, accP[m][1]);                      \
                accP[m][0] = fma2(aw, b3.x, accP[m][0]);                      \
                accP[m][1] = fma2(aw, b3.y, accP[m][1]);                      \
            }                                                                 \
        }                                                                     \
    }

// ---------------------------------------------------------------------------
// Kernel: gemmR — pre = x @ W1r + b1l  (side stream; overlaps CSR build)
// ---------------------------------------------------------------------------
__global__ __launch_bounds__(256) void gemmR_kernel(
    const float* __restrict__ x, const float* __restrict__ W1r,
    const float* __restrict__ b1l) {
    __shared__ float sB[64 * 64];
    int t  = threadIdx.x;
    int cg = t & 15;
    int ng = t >> 4;
    int nodeBase = blockIdx.x * 128 + ng * 8;

    unsigned long long accP[8][2];
#pragma unroll
    for (int m = 0; m < 8; m++) { accP[m][0] = 0ull; accP[m][1] = 0ull; }

#pragma unroll
    for (int i = 0; i < 4; i++) {
        int f4 = t + i * 256;
        ((float4*)sB)[f4] = ((const float4*)W1r)[f4];
    }
    __syncthreads();
    GEMM_CORE((const float4*)x, sB, accP, nodeBase, cg)
    float4 bias = ((const float4*)b1l)[cg];
#pragma unroll
    for (int m = 0; m < 8; m++) {
        int node = nodeBase + m;
        if (node < N_NODES) {
            float4 r;
            unpack2(accP[m][0], r.x, r.y);
            unpack2(accP[m][1], r.z, r.w);
            r.x += bias.x; r.y += bias.y; r.z += bias.z; r.w += bias.w;
            ((float4*)(g_pre + (size_t)node * 64))[cg] = r;
        }
    }
}

// ---------------------------------------------------------------------------
// Kernel 4 (PROFILED): agg_gemm12 — fused agg1 + both node GEMMs.
// Phase A: 8 warps x 16 nodes aggregate mean(xh[src]) into sH.
// Phase B: h = relu(sH @ W1l + pre) -> sH ; p2h = h@W2l fp16 ; out = h@W2r+b2l
// ---------------------------------------------------------------------------
__global__ __launch_bounds__(256) void agg_gemm12_kernel(
    const float* __restrict__ W1l,
    const float* __restrict__ W2l, const float* __restrict__ b2l,
    const float* __restrict__ W2r, float* __restrict__ out) {
    __shared__ float sB[64 * 64];     // 16 KB
    __shared__ float sH[128 * 64];    // 32 KB
    int t  = threadIdx.x;
    int w  = t >> 5;                  // warp 0..7
    unsigned lane = t & 31;
    int nodeBase = blockIdx.x * 128;

    // ---- Phase A: aggregation (agg1 inner loop, 16 nodes per warp) ----
    {
        unsigned half = lane >> 4;
        unsigned l    = lane & 15;
        const uint2* xh2 = (const uint2*)g_xh;
        for (int i = 0; i < 16; i++) {
            int node = nodeBase + w * 16 + i;
            float4 acc = make_float4(0.f, 0.f, 0.f, 0.f);
            int n = 0;
            if (node < N_NODES) {
                int row = g_rowstart[node];
                n = g_rowstart[node + 1] - row;
                const int* cs = g_csr + row;
                int k = 0;
                if (n >= 8) {
                    unsigned i0 = (unsigned)cs[0 + half] * 16u + l;
                    unsigned i1 = (unsigned)cs[2 + half] * 16u + l;
                    unsigned i2 = (unsigned)cs[4 + half] * 16u + l;
                    unsigned i3 = (unsigned)cs[6 + half] * 16u + l;
                    uint2 u0 = xh2[i0], u1 = xh2[i1], u2 = xh2[i2], u3 = xh2[i3];
                    for (; k + 16 <= n; k += 8) {
                        unsigned j0 = (unsigned)cs[k + 8  + half] * 16u + l;
                        unsigned j1 = (unsigned)cs[k + 10 + half] * 16u + l;
                        unsigned j2 = (unsigned)cs[k + 12 + half] * 16u + l;
                        unsigned j3 = (unsigned)cs[k + 14 + half] * 16u + l;
                        uint2 v0 = xh2[j0], v1 = xh2[j1], v2 = xh2[j2], v3 = xh2[j3];
                        __half2 sx = __hadd2(__hadd2(u2h(u0.x), u2h(u1.x)),
                                             __hadd2(u2h(u2.x), u2h(u3.x)));
                        __half2 sy = __hadd2(__hadd2(u2h(u0.y), u2h(u1.y)),
                                             __hadd2(u2h(u2.y), u2h(u3.y)));
                        float2 fx = __half22float2(sx);
                        float2 fy = __half22float2(sy);
                        acc.x += fx.x; acc.y += fx.y; acc.z += fy.x; acc.w += fy.y;
                        u0 = v0; u1 = v1; u2 = v2; u3 = v3;
                    }
                    {
                        __half2 sx = __hadd2(__hadd2(u2h(u0.x), u2h(u1.x)),
                                             __hadd2(u2h(u2.x), u2h(u3.x)));
                        __half2 sy = __hadd2(__hadd2(u2h(u0.y), u2h(u1.y)),
                                             __hadd2(u2h(u2.y), u2h(u3.y)));
                        float2 fx = __half22float2(sx);
                        float2 fy = __half22float2(sy);
                        acc.x += fx.x; acc.y += fx.y; acc.z += fy.x; acc.w += fy.y;
                        k += 8;
                    }
                }
                for (; k < n; k += 2) {
                    int e = k + half;
                    uint2 u = make_uint2(0u, 0u);
                    if (e < n) u = xh2[(unsigned)cs[e] * 16u + l];
                    float2 fx = u32_to_f2(u.x);
                    float2 fy = u32_to_f2(u.y);
                    acc.x += fx.x; acc.y += fx.y; acc.z += fy.x; acc.w += fy.y;
                }
            }
            acc.x += __shfl_xor_sync(0xffffffffu, acc.x, 16);
            acc.y += __shfl_xor_sync(0xffffffffu, acc.y, 16);
            acc.z += __shfl_xor_sync(0xffffffffu, acc.z, 16);
            acc.w += __shfl_xor_sync(0xffffffffu, acc.w, 16);
            if (half == 0) {
                float invd = 1.0f / (float)max(n, 1);
                float4 r;
                r.x = acc.x * invd; r.y = acc.y * invd;
                r.z = acc.z * invd; r.w = acc.w * invd;
                ((float4*)sH)[(w * 16 + i) * 16 + l] = r;
            }
        }
    }
    __syncthreads();

    // ---- Phase B ----
    int cg = t & 15;
    int ng = t >> 4;
    int lbase = ng * 8;

    // stage W1l
#pragma unroll
    for (int i = 0; i < 4; i++) {
        int f4 = t + i * 256;
        ((float4*)sB)[f4] = ((const float4*)W1l)[f4];
    }
    __syncthreads();

    unsigned long long accP[8][2];
#pragma unroll
    for (int m = 0; m < 8; m++) { accP[m][0] = 0ull; accP[m][1] = 0ull; }
    GEMM_CORE_L((const float4*)sH, sB, accP, lbase, cg)
    __syncthreads();   // all pass-1 reads of sH/sB complete

    // write h = relu(acc + pre) back to sH ; stage W2 into sB
#pragma unroll
    for (int m = 0; m < 8; m++) {
        int cn = min(nodeBase + lbase + m, N_NODES - 1);
        float4 p = ((const float4*)(g_pre + (size_t)cn * 64))[cg];
        float4 r;
        unpack2(accP[m][0], r.x, r.y);
        unpack2(accP[m][1], r.z, r.w);
        r.x = fmaxf(r.x + p.x, 0.f);
        r.y = fmaxf(r.y + p.y, 0.f);
        r.z = fmaxf(r.z + p.z, 0.f);
        r.w = fmaxf(r.w + p.w, 0.f);
        ((float4*)sH)[(lbase + m) * 16 + cg] = r;
    }
#pragma unroll
    for (int i = 0; i < 4; i++) {
        int f4 = t + i * 256;
        int k  = f4 >> 4;
        int jq = f4 & 15;
        float4 v = (jq < 8) ? ((const float4*)W2l)[k * 8 + jq]
                            : ((const float4*)W2r)[k * 8 + (jq - 8)];
        ((float4*)sB)[f4] = v;
    }
    __syncthreads();

#pragma unroll
    for (int m = 0; m < 8; m++) { accP[m][0] = 0ull; accP[m][1] = 0ull; }
    GEMM_CORE_L((const float4*)sH, sB, accP, lbase, cg)
#pragma unroll
    for (int m = 0; m < 8; m++) {
        int node = nodeBase + lbase + m;
        if (node < N_NODES) {
            float4 r;
            unpack2(accP[m][0], r.x, r.y);
            unpack2(accP[m][1], r.z, r.w);
            if (cg < 8) {
                __half2 h0 = __floats2half2_rn(r.x, r.y);
                __half2 h1 = __floats2half2_rn(r.z, r.w);
                uint2 packed = make_uint2(h2_bits(h0), h2_bits(h1));
                ((uint2*)(g_p2h + (size_t)node * 32))[cg] = packed;
            } else {
                float4 bias = ((const float4*)b2l)[cg - 8];
                r.x += bias.x; r.y += bias.y; r.z += bias.z; r.w += bias.w;
                ((float4*)(out + (size_t)node * 32))[cg - 8] = r;
            }
        }
    }
}

// ---------------------------------------------------------------------------
// Kernel 5: agg2 + final — one warp per node; 4 neighbors per round.
// Prefetch-pipelined; fp16 tree-sum. out += mean(p2h[src]).
// ---------------------------------------------------------------------------
__global__ __launch_bounds__(256) void agg2_kernel(float* __restrict__ out) {
    int warp = (blockIdx.x * blockDim.x + threadIdx.x) >> 5;
    if (warp >= N_NODES) return;
    unsigned lane = threadIdx.x & 31;
    unsigned g    = lane >> 3;
    unsigned l    = lane & 7;
    int row = g_rowstart[warp];
    int n   = g_rowstart[warp + 1] - row;
    const int* cs = g_csr + row;
    const uint2* p2 = (const uint2*)g_p2h;
    float4 acc = make_float4(0.f, 0.f, 0.f, 0.f);
    int k = 0;
    if (n >= 16) {
        unsigned i0 = (unsigned)cs[0  + g] * 8u + l;
        unsigned i1 = (unsigned)cs[4  + g] * 8u + l;
        unsigned i2 = (unsigned)cs[8  + g] * 8u + l;
        unsigned i3 = (unsigned)cs[12 + g] * 8u + l;
        uint2 u0 = p2[i0], u1 = p2[i1], u2 = p2[i2], u3 = p2[i3];
        for (; k + 32 <= n; k += 16) {
            unsigned j0 = (unsigned)cs[k + 16 + g] * 8u + l;
            unsigned j1 = (unsigned)cs[k + 20 + g] * 8u + l;
            unsigned j2 = (unsigned)cs[k + 24 + g] * 8u + l;
            unsigned j3 = (unsigned)cs[k + 28 + g] * 8u + l;
            uint2 v0 = p2[j0], v1 = p2[j1], v2 = p2[j2], v3 = p2[j3];
            __half2 sx = __hadd2(__hadd2(u2h(u0.x), u2h(u1.x)),
                                 __hadd2(u2h(u2.x), u2h(u3.x)));
            __half2 sy = __hadd2(__hadd2(u2h(u0.y), u2h(u1.y)),
                                 __hadd2(u2h(u2.y), u2h(u3.y)));
            float2 fx = __half22float2(sx);
            float2 fy = __half22float2(sy);
            acc.x += fx.x; acc.y += fx.y; acc.z += fy.x; acc.w += fy.y;
            u0 = v0; u1 = v1; u2 = v2; u3 = v3;
        }
        {
            __half2 sx = __hadd2(__hadd2(u2h(u0.x), u2h(u1.x)),
                                 __hadd2(u2h(u2.x), u2h(u3.x)));
            __half2 sy = __hadd2(__hadd2(u2h(u0.y), u2h(u1.y)),
                                 __hadd2(u2h(u2.y), u2h(u3.y)));
            float2 fx = __half22float2(sx);
            float2 fy = __half22float2(sy);
            acc.x += fx.x; acc.y += fx.y; acc.z += fy.x; acc.w += fy.y;
            k += 16;
        }
    }
    for (; k < n; k += 4) {
        int e = k + g;
        uint2 u = make_uint2(0u, 0u);
        if (e < n) u = p2[(unsigned)cs[e] * 8u + l];
        float2 fx = u32_to_f2(u.x);
        float2 fy = u32_to_f2(u.y);
        acc.x += fx.x; acc.y += fx.y; acc.z += fy.x; acc.w += fy.y;
    }
#pragma unroll
    for (int off = 8; off <= 16; off <<= 1) {
        acc.x += __shfl_xor_sync(0xffffffffu, acc.x, off);
        acc.y += __shfl_xor_sync(0xffffffffu, acc.y, off);
        acc.z += __shfl_xor_sync(0xffffffffu, acc.z, off);
        acc.w += __shfl_xor_sync(0xffffffffu, acc.w, off);
    }
    if (lane < 8) {
        float invd = 1.0f / (float)max(n, 1);
        unsigned oi = (unsigned)warp * 8u + l;
        float4 o = ((float4*)out)[oi];
        o.x = fmaf(acc.x, invd, o.x);
        o.y = fmaf(acc.y, invd, o.y);
        o.z = fmaf(acc.z, invd, o.z);
        o.w = fmaf(acc.w, invd, o.w);
        ((float4*)out)[oi] = o;
    }
}

extern "C" void kernel_launch(void* const* d_in, const int* in_sizes, int n_in,
                              void* d_out, int out_size) {
    const float* x   = (const float*)d_in[0];
    const int*   ei  = (const int*)d_in[1];   // int32
    const float* W1l = (const float*)d_in[2];
    const float* b1l = (const float*)d_in[3];
    const float* W1r = (const float*)d_in[4];
    const float* W2l = (const float*)d_in[5];
    const float* b2l = (const float*)d_in[6];
    const float* W2r = (const float*)d_in[7];
    float* out = (float*)d_out;
    int E = in_sizes[1] / 2;

    static cudaStream_t s_side = nullptr;
    static cudaEvent_t  ev_fork = nullptr, ev_join = nullptr;
    if (s_side == nullptr) {
        cudaStreamCreateWithFlags(&s_side, cudaStreamNonBlocking);
        cudaEventCreateWithFlags(&ev_fork, cudaEventDisableTiming);
        cudaEventCreateWithFlags(&ev_join, cudaEventDisableTiming);
    }

    cudaEventRecord(ev_fork, 0);
    cudaStreamWaitEvent(s_side, ev_fork, 0);

    void *p_degi, *p_cnt;
    cudaGetSymbolAddress(&p_degi, g_degi);
    cudaGetSymbolAddress(&p_cnt,  g_scan_count);
    cudaMemsetAsync(p_degi, 0, (size_t)N_NODES * sizeof(int), 0);
    cudaMemsetAsync(p_cnt,  0, sizeof(int), 0);

    int gemmBlocks = (N_NODES + 127) / 128;

    {   // kernel 1: hist + rank + x->fp16
        int tE = (E + 3) / 4;
        int tX = (N_NODES * IN_C + 7) / 8;
        int threads = tE > tX ? tE : tX;
        hist_xconv_kernel<<<(threads + 255) / 256, 256>>>(ei, x, E);
    }
    scan_fused_kernel<<<SCAN_BLOCKS, 1024>>>();       // kernel 2
    {
        int threads = (E + 3) / 4;                    // kernel 3
        fill_kernel<<<(threads + 255) / 256, 256>>>(ei, E);
    }
    // gemmR on side stream overlaps the CSR build.
    gemmR_kernel<<<gemmBlocks, 256, 0, s_side>>>(x, W1r, b1l);
    cudaEventRecord(ev_join, s_side);
    cudaStreamWaitEvent(0, ev_join, 0);

    // kernel 4 (profiled): fused agg1 + gemm12
    agg_gemm12_kernel<<<gemmBlocks, 256>>>(W1l, W2l, b2l, W2r, out);

    {   // kernel 5: agg2 + final add
        unsigned total = (unsigned)N_NODES * 32u;
        agg2_kernel<<<(total + 255) / 256, 256>>>(out);
    }
}

// round 16
// speedup vs baseline: 1.2436x; 1.2436x over previous
#include <cuda_runtime.h>
#include <cuda_fp16.h>
#include <cstdint>

#define N_NODES 100000
#define N_EDGES_MAX 3200000
#define IN_C 64
#define HID_C 64
#define OUT_C 32
#define SCAN_BLOCKS 98   // 98 * 1024 >= N_NODES

// Scratch (static __device__ arrays per harness rules)
__device__ __align__(16) float  g_sum1[(size_t)N_NODES * HID_C];  // mean-agg L1
__device__ __align__(16) float  g_pre [(size_t)N_NODES * HID_C];  // x@W1r + b1l
__device__ __align__(16) __half g_xh  [(size_t)N_NODES * IN_C];   // x in fp16
__device__ __align__(16) __half g_p2h [(size_t)N_NODES * OUT_C];  // h@W2l fp16
__device__ __align__(16) int    g_csr [N_EDGES_MAX];
__device__ __align__(16) int    g_rank[N_EDGES_MAX];
__device__ __align__(16) int    g_degi[N_NODES];
__device__ __align__(16) int    g_rowstart[N_NODES + 1];
__device__ __align__(16) int    g_bsum[SCAN_BLOCKS];
__device__ int g_scan_count;

static __device__ __forceinline__ unsigned h2_bits(__half2 h) {
    return *reinterpret_cast<const unsigned*>(&h);
}
static __device__ __forceinline__ __half2 u2h(unsigned u) {
    return *reinterpret_cast<const __half2*>(&u);
}
static __device__ __forceinline__ float2 u32_to_f2(unsigned u) {
    return __half22float2(*reinterpret_cast<const __half2*>(&u));
}
// --- packed f32x2 helpers (FFMA2; PTX-only) ---
static __device__ __forceinline__ unsigned long long dup2(float v) {
    unsigned long long r;
    asm("mov.b64 %0, {%1, %1};" : "=l"(r) : "f"(v));
    return r;
}
static __device__ __forceinline__ unsigned long long fma2(
    unsigned long long a, unsigned long long b, unsigned long long c) {
    unsigned long long d;
    asm("fma.rn.f32x2 %0, %1, %2, %3;" : "=l"(d) : "l"(a), "l"(b), "l"(c));
    return d;
}
static __device__ __forceinline__ void unpack2(unsigned long long v,
                                               float& lo, float& hi) {
    asm("mov.b64 {%0, %1}, %2;" : "=f"(lo), "=f"(hi) : "l"(v));
}

// ---------------------------------------------------------------------------
// Side kernel: x -> fp16 conversion (independent of edges).
// ---------------------------------------------------------------------------
__global__ void xconv_kernel(const float* __restrict__ x) {
    int t = blockIdx.x * blockDim.x + threadIdx.x;
    size_t xi = (size_t)t * 8;
    if (xi + 8 <= (size_t)N_NODES * IN_C) {
        float4 f0 = ((const float4*)x)[t * 2];
        float4 f1 = ((const float4*)x)[t * 2 + 1];
        __half2 h0 = __floats2half2_rn(f0.x, f0.y);
        __half2 h1 = __floats2half2_rn(f0.z, f0.w);
        __half2 h2 = __floats2half2_rn(f1.x, f1.y);
        __half2 h3 = __floats2half2_rn(f1.z, f1.w);
        uint4 packed = make_uint4(h2_bits(h0), h2_bits(h1), h2_bits(h2), h2_bits(h3));
        ((uint4*)g_xh)[t] = packed;
    }
}

// ---------------------------------------------------------------------------
// Kernel 1: degree histogram + per-edge rank. int4 edge loads.
// ---------------------------------------------------------------------------
__global__ void hist_kernel(const int* __restrict__ ei, int E) {
    int e0 = (blockIdx.x * blockDim.x + threadIdx.x) * 4;
    int d[4];
    bool full = (e0 + 4 <= E);
    if (full) {
        int4 dv = *(const int4*)(ei + (size_t)E + e0);
        d[0] = dv.x; d[1] = dv.y; d[2] = dv.z; d[3] = dv.w;
    } else {
#pragma unroll
        for (int j = 0; j < 4; j++) {
            int e = e0 + j;
            if (e < E) d[j] = ei[(size_t)E + e];
        }
    }
    int r[4];
#pragma unroll
    for (int j = 0; j < 4; j++) {
        int e = e0 + j;
        if (e < E) r[j] = atomicAdd(&g_degi[d[j]], 1);
    }
    if (full) {
        *(int4*)(g_rank + e0) = make_int4(r[0], r[1], r[2], r[3]);
    } else {
#pragma unroll
        for (int j = 0; j < 4; j++) {
            int e = e0 + j;
            if (e < E) g_rank[e] = r[j];
        }
    }
}

// ---------------------------------------------------------------------------
// Kernel 2: fused scan (single kernel, global barrier via atomic counter).
// ---------------------------------------------------------------------------
__global__ __launch_bounds__(1024) void scan_fused_kernel() {
    __shared__ int ssum[1024];
    __shared__ int sbs[128];
    __shared__ int sorig[128];
    __shared__ int s_boff;
    int t = threadIdx.x;
    int b = blockIdx.x;
    int node = b * 1024 + t;
    int v = (node < N_NODES) ? g_degi[node] : 0;
    ssum[t] = v;
    __syncthreads();
    for (int off = 1; off < 1024; off <<= 1) {
        int u = (t >= off) ? ssum[t - off] : 0;
        __syncthreads();
        ssum[t] += u;
        __syncthreads();
    }
    int lexcl = ssum[t] - v;
    if (t == 1023) {
        g_bsum[b] = ssum[t];
        __threadfence();
        atomicAdd(&g_scan_count, 1);
    }
    if (t == 0) {
        while (atomicAdd(&g_scan_count, 0) < SCAN_BLOCKS) { }
    }
    __syncthreads();
    __threadfence();
    int bv = (t < SCAN_BLOCKS) ? g_bsum[t] : 0;
    if (t < 128) { sbs[t] = bv; sorig[t] = bv; }
    __syncthreads();
    for (int off = 1; off < 128; off <<= 1) {
        int u = (t >= off && t < 128) ? sbs[t - off] : 0;
        __syncthreads();
        if (t < 128) sbs[t] += u;
        __syncthreads();
    }
    if (t == 0) s_boff = sbs[b] - sorig[b];
    __syncthreads();
    if (node < N_NODES) g_rowstart[node] = lexcl + s_boff;
    if (b == 0 && t == 0) g_rowstart[N_NODES] = sbs[SCAN_BLOCKS - 1];
}

// ---------------------------------------------------------------------------
// Kernel 3: fill CSR — no atomics; int4 loads for src/dst/rank.
// ---------------------------------------------------------------------------
__global__ void fill_kernel(const int* __restrict__ ei, int E) {
    int e0 = (blockIdx.x * blockDim.x + threadIdx.x) * 4;
    int s[4], d[4], r[4];
    bool full = (e0 + 4 <= E);
    if (full) {
        int4 sv = *(const int4*)(ei + e0);
        int4 dv = *(const int4*)(ei + (size_t)E + e0);
        int4 rv = *(const int4*)(g_rank + e0);
        s[0] = sv.x; s[1] = sv.y; s[2] = sv.z; s[3] = sv.w;
        d[0] = dv.x; d[1] = dv.y; d[2] = dv.z; d[3] = dv.w;
        r[0] = rv.x; r[1] = rv.y; r[2] = rv.z; r[3] = rv.w;
    } else {
#pragma unroll
        for (int j = 0; j < 4; j++) {
            int e = e0 + j;
            if (e < E) {
                s[j] = ei[e];
                d[j] = ei[(size_t)E + e];
                r[j] = g_rank[e];
            }
        }
    }
    int base[4];
#pragma unroll
    for (int j = 0; j < 4; j++) {
        int e = e0 + j;
        if (e < E) base[j] = g_rowstart[d[j]];
    }
#pragma unroll
    for (int j = 0; j < 4; j++) {
        int e = e0 + j;
        if (e < E) g_csr[base[j] + r[j]] = s[j];
    }
}

// ---------------------------------------------------------------------------
// Kernel: agg1 — one warp per dst node; 2 neighbors per round.
// Prefetch-pipelined; fp16 tree-sum over each 4-neighbor group.
// ---------------------------------------------------------------------------
__global__ __launch_bounds__(256) void agg1_kernel() {
    int warp = (blockIdx.x * blockDim.x + threadIdx.x) >> 5;
    if (warp >= N_NODES) return;
    unsigned lane = threadIdx.x & 31;
    unsigned half = lane >> 4;
    unsigned l    = lane & 15;
    int row = g_rowstart[warp];
    int n   = g_rowstart[warp + 1] - row;
    const int* cs = g_csr + row;
    const uint2* xh2 = (const uint2*)g_xh;
    float4 acc = make_float4(0.f, 0.f, 0.f, 0.f);
    int k = 0;
    if (n >= 8) {
        unsigned i0 = (unsigned)cs[0 + half] * 16u + l;
        unsigned i1 = (unsigned)cs[2 + half] * 16u + l;
        unsigned i2 = (unsigned)cs[4 + half] * 16u + l;
        unsigned i3 = (unsigned)cs[6 + half] * 16u + l;
        uint2 u0 = xh2[i0], u1 = xh2[i1], u2 = xh2[i2], u3 = xh2[i3];
        for (; k + 16 <= n; k += 8) {
            unsigned j0 = (unsigned)cs[k + 8  + half] * 16u + l;
            unsigned j1 = (unsigned)cs[k + 10 + half] * 16u + l;
            unsigned j2 = (unsigned)cs[k + 12 + half] * 16u + l;
            unsigned j3 = (unsigned)cs[k + 14 + half] * 16u + l;
            uint2 v0 = xh2[j0], v1 = xh2[j1], v2 = xh2[j2], v3 = xh2[j3];
            __half2 sx = __hadd2(__hadd2(u2h(u0.x), u2h(u1.x)),
                                 __hadd2(u2h(u2.x), u2h(u3.x)));
            __half2 sy = __hadd2(__hadd2(u2h(u0.y), u2h(u1.y)),
                                 __hadd2(u2h(u2.y), u2h(u3.y)));
            float2 fx = __half22float2(sx);
            float2 fy = __half22float2(sy);
            acc.x += fx.x; acc.y += fx.y; acc.z += fy.x; acc.w += fy.y;
            u0 = v0; u1 = v1; u2 = v2; u3 = v3;
        }
        {   // drain the prefetched batch
            __half2 sx = __hadd2(__hadd2(u2h(u0.x), u2h(u1.x)),
                                 __hadd2(u2h(u2.x), u2h(u3.x)));
            __half2 sy = __hadd2(__hadd2(u2h(u0.y), u2h(u1.y)),
                                 __hadd2(u2h(u2.y), u2h(u3.y)));
            float2 fx = __half22float2(sx);
            float2 fy = __half22float2(sy);
            acc.x += fx.x; acc.y += fx.y; acc.z += fy.x; acc.w += fy.y;
            k += 8;
        }
    }
    for (; k < n; k += 2) {
        int e = k + half;
        uint2 u = make_uint2(0u, 0u);
        if (e < n) u = xh2[(unsigned)cs[e] * 16u + l];
        float2 fx = u32_to_f2(u.x);
        float2 fy = u32_to_f2(u.y);
        acc.x += fx.x; acc.y += fx.y; acc.z += fy.x; acc.w += fy.y;
    }
    acc.x += __shfl_xor_sync(0xffffffffu, acc.x, 16);
    acc.y += __shfl_xor_sync(0xffffffffu, acc.y, 16);
    acc.z += __shfl_xor_sync(0xffffffffu, acc.z, 16);
    acc.w += __shfl_xor_sync(0xffffffffu, acc.w, 16);
    if (half == 0) {
        float invd = 1.0f / (float)max(n, 1);
        float4 r;
        r.x = acc.x * invd; r.y = acc.y * invd;
        r.z = acc.z * invd; r.w = acc.w * invd;
        ((float4*)g_sum1)[(unsigned)warp * 16u + l] = r;
    }
}

// ---------------------------------------------------------------------------
// FFMA2 GEMM cores.
// ---------------------------------------------------------------------------
#define GEMM_CORE(A4, sB, accP, nodeBase, cg)                                 \
    {                                                                         \
        const ulonglong2* sBp = (const ulonglong2*)(sB);                      \
        _Pragma("unroll 4")                                                   \
        for (int k4 = 0; k4 < 16; k4++) {                                     \
            ulonglong2 b0 = sBp[(k4 * 4 + 0) * 16 + (cg)];                    \
            ulonglong2 b1 = sBp[(k4 * 4 + 1) * 16 + (cg)];                    \
            ulonglong2 b2 = sBp[(k4 * 4 + 2) * 16 + (cg)];                    \
            ulonglong2 b3 = sBp[(k4 * 4 + 3) * 16 + (cg)];                    \
            _Pragma("unroll")                                                 \
            for (int m = 0; m < 8; m++) {                                     \
                int node = min((nodeBase) + m, N_NODES - 1);                  \
                float4 a = (A4)[(size_t)node * 16 + k4];                      \
                unsigned long long ax = dup2(a.x), ay = dup2(a.y);            \
                unsigned long long az = dup2(a.z), aw = dup2(a.w);            \
                accP[m][0] = fma2(ax, b0.x, accP[m][0]);                      \
                accP[m][1] = fma2(ax, b0.y, accP[m][1]);                      \
                accP[m][0] = fma2(ay, b1.x, accP[m][0]);                      \
                accP[m][1] = fma2(ay, b1.y, accP[m][1]);                      \
                accP[m][0] = fma2(az, b2.x, accP[m][0]);                      \
                accP[m][1] = fma2(az, b2.y, accP[m][1]);                      \
                accP[m][0] = fma2(aw, b3.x, accP[m][0]);                      \
                accP[m][1] = fma2(aw, b3.y, accP[m][1]);                      \
            }                                                                 \
        }                                                                     \
    }

#define GEMM_CORE_L(A4, sB, accP, lbase, cg)                                  \
    {                                                                         \
        const ulonglong2* sBp = (const ulonglong2*)(sB);                      \
        _Pragma("unroll 4")                                                   \
        for (int k4 = 0; k4 < 16; k4++) {                                     \
            ulonglong2 b0 = sBp[(k4 * 4 + 0) * 16 + (cg)];                    \
            ulonglong2 b1 = sBp[(k4 * 4 + 1) * 16 + (cg)];                    \
            ulonglong2 b2 = sBp[(k4 * 4 + 2) * 16 + (cg)];                    \
            ulonglong2 b3 = sBp[(k4 * 4 + 3) * 16 + (cg)];                    \
            _Pragma("unroll")                                                 \
            for (int m = 0; m < 8; m++) {                                     \
                int lrow = (lbase) + m;                                       \
                float4 a = (A4)[lrow * 16 + k4];                              \
                unsigned long long ax = dup2(a.x), ay = dup2(a.y);            \
                unsigned long long az = dup2(a.z), aw = dup2(a.w);            \
                accP[m][0] = fma2(ax, b0.x, accP[m][0]);                      \
                accP[m][1] = fma2(ax, b0.y, accP[m][1]);                      \
                accP[m][0] = fma2(ay, b1.x, accP[m][0]);                      \
                accP[m][1] = fma2(ay, b1.y, accP[m][1]);                      \
                accP[m][0] = fma2(az, b2.x, accP[m][0]);                      \
                accP[m][1] = fma2(az, b2.y, accP[m][1]);                      \
                accP[m][0] = fma2(aw, b3.x, accP[m][0]);                      \
                accP[m][1] = fma2(aw, b3.y, accP[m][1]);                      \
            }                                                                 \
        }                                                                     \
    }

// ---------------------------------------------------------------------------
// Kernel: gemmR — pre = x @ W1r + b1l  (side stream; overlaps CSR build)
// ---------------------------------------------------------------------------
__global__ __launch_bounds__(256) void gemmR_kernel(
    const float* __restrict__ x, const float* __restrict__ W1r,
    const float* __restrict__ b1l) {
    __shared__ float sB[64 * 64];
    int t  = threadIdx.x;
    int cg = t & 15;
    int ng = t >> 4;
    int nodeBase = blockIdx.x * 128 + ng * 8;

    unsigned long long accP[8][2];
#pragma unroll
    for (int m = 0; m < 8; m++) { accP[m][0] = 0ull; accP[m][1] = 0ull; }

#pragma unroll
    for (int i = 0; i < 4; i++) {
        int f4 = t + i * 256;
        ((float4*)sB)[f4] = ((const float4*)W1r)[f4];
    }
    __syncthreads();
    GEMM_CORE((const float4*)x, sB, accP, nodeBase, cg)
    float4 bias = ((const float4*)b1l)[cg];
#pragma unroll
    for (int m = 0; m < 8; m++) {
        int node = nodeBase + m;
        if (node < N_NODES) {
            float4 r;
            unpack2(accP[m][0], r.x, r.y);
            unpack2(accP[m][1], r.z, r.w);
            r.x += bias.x; r.y += bias.y; r.z += bias.z; r.w += bias.w;
            ((float4*)(g_pre + (size_t)node * 64))[cg] = r;
        }
    }
}

// ---------------------------------------------------------------------------
// Kernel: gemm12 — fused layer-1 + layer-2 node GEMMs (h kept in smem).
// ---------------------------------------------------------------------------
__global__ __launch_bounds__(256) void gemm12_kernel(
    const float* __restrict__ W1l,
    const float* __restrict__ W2l, const float* __restrict__ b2l,
    const float* __restrict__ W2r, float* __restrict__ out) {
    __shared__ float sB[64 * 64];     // 16 KB
    __shared__ float sH[128 * 64];    // 32 KB
    int t  = threadIdx.x;
    int cg = t & 15;
    int ng = t >> 4;
    int nodeBase = blockIdx.x * 128 + ng * 8;

    unsigned long long accP[8][2];
#pragma unroll
    for (int m = 0; m < 8; m++) { accP[m][0] = 0ull; accP[m][1] = 0ull; }

    // ---- pass 1: h = relu(sum1 @ W1l + pre) ----
#pragma unroll
    for (int i = 0; i < 4; i++) {
        int f4 = t + i * 256;
        ((float4*)sB)[f4] = ((const float4*)W1l)[f4];
    }
    __syncthreads();
    GEMM_CORE((const float4*)g_sum1, sB, accP, nodeBase, cg)
#pragma unroll
    for (int m = 0; m < 8; m++) {
        int cn = min(nodeBase + m, N_NODES - 1);
        float4 p = ((const float4*)(g_pre + (size_t)cn * 64))[cg];
        float4 r;
        unpack2(accP[m][0], r.x, r.y);
        unpack2(accP[m][1], r.z, r.w);
        r.x = fmaxf(r.x + p.x, 0.f);
        r.y = fmaxf(r.y + p.y, 0.f);
        r.z = fmaxf(r.z + p.z, 0.f);
        r.w = fmaxf(r.w + p.w, 0.f);
        ((float4*)(sH + (ng * 8 + m) * 64))[cg] = r;
    }
    __syncthreads();

    // ---- pass 2 ----
#pragma unroll
    for (int i = 0; i < 4; i++) {
        int f4 = t + i * 256;
        int k  = f4 >> 4;
        int jq = f4 & 15;
        float4 v = (jq < 8) ? ((const float4*)W2l)[k * 8 + jq]
                            : ((const float4*)W2r)[k * 8 + (jq - 8)];
        ((float4*)sB)[f4] = v;
    }
#pragma unroll
    for (int m = 0; m < 8; m++) { accP[m][0] = 0ull; accP[m][1] = 0ull; }
    __syncthreads();
    GEMM_CORE_L((const float4*)sH, sB, accP, ng * 8, cg)
#pragma unroll
    for (int m = 0; m < 8; m++) {
        int node = nodeBase + m;
        if (node < N_NODES) {
            float4 r;
            unpack2(accP[m][0], r.x, r.y);
            unpack2(accP[m][1], r.z, r.w);
            if (cg < 8) {
                __half2 h0 = __floats2half2_rn(r.x, r.y);
                __half2 h1 = __floats2half2_rn(r.z, r.w);
                uint2 packed = make_uint2(h2_bits(h0), h2_bits(h1));
                ((uint2*)(g_p2h + (size_t)node * 32))[cg] = packed;
            } else {
                float4 bias = ((const float4*)b2l)[cg - 8];
                r.x += bias.x; r.y += bias.y; r.z += bias.z; r.w += bias.w;
                ((float4*)(out + (size_t)node * 32))[cg - 8] = r;
            }
        }
    }
}

// ---------------------------------------------------------------------------
// Kernel: agg2 + final — one warp per node; 4 neighbors per round.
// Prefetch-pipelined; fp16 tree-sum. out += mean(p2h[src]).
// ---------------------------------------------------------------------------
__global__ __launch_bounds__(256) void agg2_kernel(float* __restrict__ out) {
    int warp = (blockIdx.x * blockDim.x + threadIdx.x) >> 5;
    if (warp >= N_NODES) return;
    unsigned lane = threadIdx.x & 31;
    unsigned g    = lane >> 3;
    unsigned l    = lane & 7;
    int row = g_rowstart[warp];
    int n   = g_rowstart[warp + 1] - row;
    const int* cs = g_csr + row;
    const uint2* p2 = (const uint2*)g_p2h;
    float4 acc = make_float4(0.f, 0.f, 0.f, 0.f);
    int k = 0;
    if (n >= 16) {
        unsigned i0 = (unsigned)cs[0  + g] * 8u + l;
        unsigned i1 = (unsigned)cs[4  + g] * 8u + l;
        unsigned i2 = (unsigned)cs[8  + g] * 8u + l;
        unsigned i3 = (unsigned)cs[12 + g] * 8u + l;
        uint2 u0 = p2[i0], u1 = p2[i1], u2 = p2[i2], u3 = p2[i3];
        for (; k + 32 <= n; k += 16) {
            unsigned j0 = (unsigned)cs[k + 16 + g] * 8u + l;
            unsigned j1 = (unsigned)cs[k + 20 + g] * 8u + l;
            unsigned j2 = (unsigned)cs[k + 24 + g] * 8u + l;
            unsigned j3 = (unsigned)cs[k + 28 + g] * 8u + l;
            uint2 v0 = p2[j0], v1 = p2[j1], v2 = p2[j2], v3 = p2[j3];
            __half2 sx = __hadd2(__hadd2(u2h(u0.x), u2h(u1.x)),
                                 __hadd2(u2h(u2.x), u2h(u3.x)));
            __half2 sy = __hadd2(__hadd2(u2h(u0.y), u2h(u1.y)),
                                 __hadd2(u2h(u2.y), u2h(u3.y)));
            float2 fx = __half22float2(sx);
            float2 fy = __half22float2(sy);
            acc.x += fx.x; acc.y += fx.y; acc.z += fy.x; acc.w += fy.y;
            u0 = v0; u1 = v1; u2 = v2; u3 = v3;
        }
        {
            __half2 sx = __hadd2(__hadd2(u2h(u0.x), u2h(u1.x)),
                                 __hadd2(u2h(u2.x), u2h(u3.x)));
            __half2 sy = __hadd2(__hadd2(u2h(u0.y), u2h(u1.y)),
                                 __hadd2(u2h(u2.y), u2h(u3.y)));
            float2 fx = __half22float2(sx);
            float2 fy = __half22float2(sy);
            acc.x += fx.x; acc.y += fx.y; acc.z += fy.x; acc.w += fy.y;
            k += 16;
        }
    }
    for (; k < n; k += 4) {
        int e = k + g;
        uint2 u = make_uint2(0u, 0u);
        if (e < n) u = p2[(unsigned)cs[e] * 8u + l];
        float2 fx = u32_to_f2(u.x);
        float2 fy = u32_to_f2(u.y);
        acc.x += fx.x; acc.y += fx.y; acc.z += fy.x; acc.w += fy.y;
    }
#pragma unroll
    for (int off = 8; off <= 16; off <<= 1) {
        acc.x += __shfl_xor_sync(0xffffffffu, acc.x, off);
        acc.y += __shfl_xor_sync(0xffffffffu, acc.y, off);
        acc.z += __shfl_xor_sync(0xffffffffu, acc.z, off);
        acc.w += __shfl_xor_sync(0xffffffffu, acc.w, off);
    }
    if (lane < 8) {
        float invd = 1.0f / (float)max(n, 1);
        unsigned oi = (unsigned)warp * 8u + l;
        float4 o = ((float4*)out)[oi];
        o.x = fmaf(acc.x, invd, o.x);
        o.y = fmaf(acc.y, invd, o.y);
        o.z = fmaf(acc.z, invd, o.z);
        o.w = fmaf(acc.w, invd, o.w);
        ((float4*)out)[oi] = o;
    }
}

extern "C" void kernel_launch(void* const* d_in, const int* in_sizes, int n_in,
                              void* d_out, int out_size) {
    const float* x   = (const float*)d_in[0];
    const int*   ei  = (const int*)d_in[1];   // int32
    const float* W1l = (const float*)d_in[2];
    const float* b1l = (const float*)d_in[3];
    const float* W1r = (const float*)d_in[4];
    const float* W2l = (const float*)d_in[5];
    const float* b2l = (const float*)d_in[6];
    const float* W2r = (const float*)d_in[7];
    float* out = (float*)d_out;
    int E = in_sizes[1] / 2;

    static cudaStream_t s_side = nullptr;
    static cudaEvent_t  ev_fork = nullptr, ev_join = nullptr;
    if (s_side == nullptr) {
        cudaStreamCreateWithFlags(&s_side, cudaStreamNonBlocking);
        cudaEventCreateWithFlags(&ev_fork, cudaEventDisableTiming);
        cudaEventCreateWithFlags(&ev_join, cudaEventDisableTiming);
    }

    cudaEventRecord(ev_fork, 0);
    cudaStreamWaitEvent(s_side, ev_fork, 0);

    void *p_degi, *p_cnt;
    cudaGetSymbolAddress(&p_degi, g_degi);
    cudaGetSymbolAddress(&p_cnt,  g_scan_count);
    cudaMemsetAsync(p_degi, 0, (size_t)N_NODES * sizeof(int), 0);
    cudaMemsetAsync(p_cnt,  0, sizeof(int), 0);

    int gemmBlocks = (N_NODES + 127) / 128;

    // Side stream: x->fp16 conversion, then pre = x@W1r + b1l.
    {
        int tX = (N_NODES * IN_C + 7) / 8;
        xconv_kernel<<<(tX + 255) / 256, 256, 0, s_side>>>(x);
    }
    gemmR_kernel<<<gemmBlocks, 256, 0, s_side>>>(x, W1r, b1l);
    cudaEventRecord(ev_join, s_side);

    {   // kernel: hist (edges only)
        int threads = (E + 3) / 4;
        hist_kernel<<<(threads + 255) / 256, 256>>>(ei, E);
    }
    scan_fused_kernel<<<SCAN_BLOCKS, 1024>>>();
    {
        int threads = (E + 3) / 4;
        fill_kernel<<<(threads + 255) / 256, 256>>>(ei, E);
    }
    // agg1 needs g_xh (side stream) + CSR: join here.
    cudaStreamWaitEvent(0, ev_join, 0);
    {   // agg1
        unsigned total = (unsigned)N_NODES * 32u;
        agg1_kernel<<<(total + 255) / 256, 256>>>();
    }
    gemm12_kernel<<<gemmBlocks, 256>>>(W1l, W2l, b2l, W2r, out);
    {   // agg2 + final add
        unsigned total = (unsigned)N_NODES * 32u;
        agg2_kernel<<<(total + 255) / 256, 256>>>(out);
    }
}